// round 11
// baseline (speedup 1.0000x reference)
#include <cuda_runtime.h>
#include <cuda_fp16.h>
#include <cuda_bf16.h>
#include <cstdint>
#include <math.h>

// Problem constants (match reference setup_inputs)
#define NN    50000
#define EE    800000
#define INF_  128
#define HID   64
#define OUTC  128
#define HEADS 4
#define SLOPE 0.2f

#define ETOT (EE + NN)

// ---------------- static device scratch (no allocs allowed) ----------------
__device__ __align__(16) __half g_h1h  [NN * HEADS * HID];  // fp16 h1 (gather)
__device__ __align__(16) __half g_out1h[NN * HEADS * HID];  // fp16 relu(agg+b1)
__device__ __align__(16) float  g_as1 [NN * HEADS];
__device__ __align__(16) float  g_ad1 [NN * HEADS];
__device__ __align__(16) __half g_h2h [NN * OUTC];          // fp16 h2 (gather)
__device__ __align__(16) float  g_as2 [NN];
__device__ __align__(16) float  g_ad2 [NN];

__device__ __align__(16) int   g_cnt [NN];      // degree counts / scatter cursor
__device__ __align__(16) int   g_off [NN + 1];  // CSR row offsets (by dst)
__device__ __align__(16) int   g_part[64];      // per-block totals from scan1
__device__ __align__(16) int   g_csr [ETOT];    // src node per CSR-sorted edge

// ---------------- helpers ----------------
__device__ __forceinline__ float lrelu(float x) { return x >= 0.f ? x : SLOPE * x; }

__device__ __forceinline__ uint32_t pack2bf(float a, float b) {
    __nv_bfloat162 p = __floats2bfloat162_rn(a, b);
    return *reinterpret_cast<uint32_t*>(&p);
}
__device__ __forceinline__ float bf_res(float x) {
    __nv_bfloat16 h = __float2bfloat16(x);
    return x - __bfloat162float(h);
}

__device__ __forceinline__ void h2fma(uint32_t u, float w, float& a, float& b) {
    __half2 h = *(__half2*)&u;
    float2 f = __half22float2(h);
    a = fmaf(f.x, w, a);
    b = fmaf(f.y, w, b);
}

#define MMA_BF16(c, a0, a1, a2, a3, b0, b1)                                  \
    asm volatile("mma.sync.aligned.m16n8k16.row.col.f32.bf16.bf16.f32 "      \
                 "{%0,%1,%2,%3}, {%4,%5,%6,%7}, {%8,%9}, {%0,%1,%2,%3};"     \
                 : "+f"(c[0]), "+f"(c[1]), "+f"(c[2]), "+f"(c[3])            \
                 : "r"(a0), "r"(a1), "r"(a2), "r"(a3), "r"(b0), "r"(b1))

// ============================================================================
// CSR build (runs on side stream sB), 4 edges/thread for atomic MLP
// ============================================================================
__global__ void count_kernel(const int* __restrict__ ei, int E, int Etot,
                             int* __restrict__ cnt) {
    int base = (blockIdx.x * blockDim.x + threadIdx.x) * 4;
    if (base >= Etot) return;
    if (base + 4 <= E && (E & 3) == 0) {
        int4 d4 = *(const int4*)(ei + E + base);
        atomicAdd(cnt + d4.x, 1);
        atomicAdd(cnt + d4.y, 1);
        atomicAdd(cnt + d4.z, 1);
        atomicAdd(cnt + d4.w, 1);
    } else {
#pragma unroll
        for (int j = 0; j < 4; j++) {
            int e = base + j;
            if (e < Etot) {
                int d = (e < E) ? ei[E + e] : (e - E);
                atomicAdd(cnt + d, 1);
            }
        }
    }
}

__global__ void scan1_kernel(const int* __restrict__ cnt, int* __restrict__ off,
                             int* __restrict__ part, int n) {
    __shared__ int wsum[32];
    int tid = threadIdx.x;
    int i = blockIdx.x * 1024 + tid;
    int lane = tid & 31, w = tid >> 5;
    int v = (i < n) ? cnt[i] : 0;
    int x = v;
#pragma unroll
    for (int o = 1; o < 32; o <<= 1) {
        int y = __shfl_up_sync(0xffffffffu, x, o);
        if (lane >= o) x += y;
    }
    if (lane == 31) wsum[w] = x;
    __syncthreads();
    if (w == 0) {
        int s = wsum[lane];
#pragma unroll
        for (int o = 1; o < 32; o <<= 1) {
            int y = __shfl_up_sync(0xffffffffu, s, o);
            if (lane >= o) s += y;
        }
        wsum[lane] = s;
    }
    __syncthreads();
    int incl = x + (w > 0 ? wsum[w - 1] : 0);
    if (i < n) off[i + 1] = incl;
    if (tid == 1023) part[blockIdx.x] = incl;
}

__global__ void scan_fix_kernel(int* __restrict__ off, int* __restrict__ cnt,
                                const int* __restrict__ part, int n) {
    __shared__ int wsum2[2];
    __shared__ int base_s;
    int b = blockIdx.x;
    int tid = threadIdx.x;
    if (tid < 64) {
        int v = (tid < b) ? part[tid] : 0;
#pragma unroll
        for (int o = 16; o; o >>= 1) v += __shfl_xor_sync(0xffffffffu, v, o);
        if ((tid & 31) == 0) wsum2[tid >> 5] = v;
    }
    __syncthreads();
    if (tid == 0) base_s = wsum2[0] + wsum2[1];
    __syncthreads();
    int base = base_s;
    int i = b * 1024 + tid;
    if (b == 0 && tid == 0) { off[0] = 0; cnt[0] = 0; }
    if (i < n) {
        int o = off[i + 1] + base;
        off[i + 1] = o;
        if (i + 1 < n) cnt[i + 1] = o;
    }
}

__global__ void scatter_kernel(const int* __restrict__ ei, int E, int Etot,
                               int* __restrict__ cur, int* __restrict__ csr) {
    int base = (blockIdx.x * blockDim.x + threadIdx.x) * 4;
    if (base >= Etot) return;
    if (base + 4 <= E && (E & 3) == 0) {
        int4 s4 = *(const int4*)(ei + base);
        int4 d4 = *(const int4*)(ei + E + base);
        int p0 = atomicAdd(cur + d4.x, 1);
        int p1 = atomicAdd(cur + d4.y, 1);
        int p2 = atomicAdd(cur + d4.z, 1);
        int p3 = atomicAdd(cur + d4.w, 1);
        csr[p0] = s4.x; csr[p1] = s4.y; csr[p2] = s4.z; csr[p3] = s4.w;
    } else {
#pragma unroll
        for (int j = 0; j < 4; j++) {
            int e = base + j;
            if (e < Etot) {
                int s, d;
                if (e < E) { s = ei[e]; d = ei[E + e]; } else { s = e - E; d = s; }
                int pos = atomicAdd(cur + d, 1);
                csr[pos] = s;
            }
        }
    }
}

// ============================================================================
// 3xBF16 tensor-core GEMM, fp16 output, fused attention-coefficient epilogue.
// AT: fp32 or fp16 A operand. NHEADS: heads covered per block (BN=128):
//   1 -> as_out[row] = C_row(block cols) . av   (layer 2, N=128)
//   2 -> block cols split at 64; as_out[row*4 + bx*2 + bin]   (layer 1, N=256)
// ============================================================================
#define BM 128
#define BN 128
#define BK 16
#define AST 12
#define BST 13

template <typename AT, int NHEADS>
__global__ __launch_bounds__(256) void gemmbf3_kernel(
    const AT* __restrict__ A, const float* __restrict__ B,
    __half* __restrict__ Ch,
    const float* __restrict__ av_src, const float* __restrict__ av_dst,
    float* __restrict__ as_out, float* __restrict__ ad_out,
    int M, int N, int K)
{
    __shared__ uint32_t Ah[BM * AST], Al[BM * AST];
    __shared__ uint32_t Bh[BN * BST], Bl[BN * BST];
    __shared__ float sAs[4][BM], sAd[4][BM];

    int tid  = threadIdx.x;
    int bm   = blockIdx.y * BM;
    int bn   = blockIdx.x * BN;
    int warp = tid >> 5, lane = tid & 31;
    int wm = (warp & 1) * 64;
    int wn = (warp >> 1) * 32;
    int g = lane >> 2, t = lane & 3;

    float acc[4][4][4];
#pragma unroll
    for (int mi = 0; mi < 4; mi++)
#pragma unroll
        for (int ni = 0; ni < 4; ni++)
#pragma unroll
            for (int j = 0; j < 4; j++) acc[mi][ni][j] = 0.f;

    float4 ra[2], rb0, rb1;
    int c0 = (tid & 31) * 4;
    int kp = tid >> 5;

    auto loadTiles = [&](int kt) {
#pragma unroll
        for (int t2 = 0; t2 < 2; t2++) {
            int f = tid + t2 * 256;
            int r = f >> 2, kc = (f & 3) * 4;
            int row = bm + r;
            if (row < M) {
                if constexpr (sizeof(AT) == 4) {
                    ra[t2] = *(const float4*)((const float*)A + (size_t)row * K + kt + kc);
                } else {
                    uint2 u = *(const uint2*)((const __half*)A + (size_t)row * K + kt + kc);
                    float2 f0 = __half22float2(*(__half2*)&u.x);
                    float2 f1 = __half22float2(*(__half2*)&u.y);
                    ra[t2] = make_float4(f0.x, f0.y, f1.x, f1.y);
                }
            } else {
                ra[t2] = make_float4(0.f, 0.f, 0.f, 0.f);
            }
        }
        rb0 = *(const float4*)(B + (size_t)(kt + 2 * kp) * N + bn + c0);
        rb1 = *(const float4*)(B + (size_t)(kt + 2 * kp + 1) * N + bn + c0);
    };

    auto storeTiles = [&]() {
#pragma unroll
        for (int t2 = 0; t2 < 2; t2++) {
            int f = tid + t2 * 256;
            int r = f >> 2, kc = (f & 3) * 4;
            float v0 = (&ra[t2].x)[0], v1 = (&ra[t2].x)[1];
            float v2 = (&ra[t2].x)[2], v3 = (&ra[t2].x)[3];
            int w = r * AST + (kc >> 1);
            Ah[w]     = pack2bf(v0, v1);
            Ah[w + 1] = pack2bf(v2, v3);
            Al[w]     = pack2bf(bf_res(v0), bf_res(v1));
            Al[w + 1] = pack2bf(bf_res(v2), bf_res(v3));
        }
        float q0[4] = {rb0.x, rb0.y, rb0.z, rb0.w};
        float q1[4] = {rb1.x, rb1.y, rb1.z, rb1.w};
#pragma unroll
        for (int j = 0; j < 4; j++) {
            Bh[(c0 + j) * BST + kp] = pack2bf(q0[j], q1[j]);
            Bl[(c0 + j) * BST + kp] = pack2bf(bf_res(q0[j]), bf_res(q1[j]));
        }
    };

    loadTiles(0);
    storeTiles();
    __syncthreads();

    for (int kt = 0; kt < K; kt += BK) {
        bool nx = (kt + BK) < K;
        if (nx) loadTiles(kt + BK);

        uint32_t bh0[4], bh1[4], bl0[4], bl1[4];
#pragma unroll
        for (int ni = 0; ni < 4; ni++) {
            int cw = (wn + ni * 8 + g) * BST;
            bh0[ni] = Bh[cw + t]; bh1[ni] = Bh[cw + 4 + t];
            bl0[ni] = Bl[cw + t]; bl1[ni] = Bl[cw + 4 + t];
        }
#pragma unroll
        for (int mi = 0; mi < 4; mi++) {
            int r0w = (wm + mi * 16 + g) * AST;
            int r1w = r0w + 8 * AST;
            uint32_t ah0 = Ah[r0w + t],     ah1 = Ah[r1w + t];
            uint32_t ah2 = Ah[r0w + 4 + t], ah3 = Ah[r1w + 4 + t];
            uint32_t al0 = Al[r0w + t],     al1 = Al[r1w + t];
            uint32_t al2 = Al[r0w + 4 + t], al3 = Al[r1w + 4 + t];
#pragma unroll
            for (int ni = 0; ni < 4; ni++) {
                MMA_BF16(acc[mi][ni], ah0, ah1, ah2, ah3, bh0[ni], bh1[ni]);
                MMA_BF16(acc[mi][ni], ah0, ah1, ah2, ah3, bl0[ni], bl1[ni]);
                MMA_BF16(acc[mi][ni], al0, al1, al2, al3, bh0[ni], bh1[ni]);
            }
        }
        __syncthreads();
        if (nx) {
            storeTiles();
        }
        __syncthreads();
    }

    // ---- epilogue: fp16 store ----
#pragma unroll
    for (int mi = 0; mi < 4; mi++) {
#pragma unroll
        for (int ni = 0; ni < 4; ni++) {
            int row = bm + wm + mi * 16 + g;
            int col = bn + wn + ni * 8 + 2 * t;
            if (row < M)
                *(__half2*)(Ch + (size_t)row * N + col) =
                    __floats2half2_rn(acc[mi][ni][0], acc[mi][ni][1]);
            if (row + 8 < M)
                *(__half2*)(Ch + (size_t)(row + 8) * N + col) =
                    __floats2half2_rn(acc[mi][ni][2], acc[mi][ni][3]);
        }
    }

    // ---- fused attention-coefficient epilogue ----
    {
        float pas[4][2] = {{0.f,0.f},{0.f,0.f},{0.f,0.f},{0.f,0.f}};
        float pad_[4][2] = {{0.f,0.f},{0.f,0.f},{0.f,0.f},{0.f,0.f}};
#pragma unroll
        for (int ni = 0; ni < 4; ni++) {
#pragma unroll
            for (int j2 = 0; j2 < 2; j2++) {
                int colL = wn + ni * 8 + 2 * t + j2;
                float a = av_src[bn + colL];
                float b = av_dst[bn + colL];
#pragma unroll
                for (int mi = 0; mi < 4; mi++) {
                    pas[mi][0] = fmaf(acc[mi][ni][j2],     a, pas[mi][0]);
                    pas[mi][1] = fmaf(acc[mi][ni][2 + j2], a, pas[mi][1]);
                    pad_[mi][0] = fmaf(acc[mi][ni][j2],     b, pad_[mi][0]);
                    pad_[mi][1] = fmaf(acc[mi][ni][2 + j2], b, pad_[mi][1]);
                }
            }
        }
#pragma unroll
        for (int off = 1; off < 4; off <<= 1) {
#pragma unroll
            for (int mi = 0; mi < 4; mi++) {
#pragma unroll
                for (int h = 0; h < 2; h++) {
                    pas[mi][h] += __shfl_xor_sync(0xffffffffu, pas[mi][h], off);
                    pad_[mi][h] += __shfl_xor_sync(0xffffffffu, pad_[mi][h], off);
                }
            }
        }
        if (t == 0) {
            int q = warp >> 1;   // = wn/32; rows disjoint between warp pairs
#pragma unroll
            for (int mi = 0; mi < 4; mi++) {
#pragma unroll
                for (int h = 0; h < 2; h++) {
                    int row = wm + mi * 16 + h * 8 + g;
                    sAs[q][row] = pas[mi][h];
                    sAd[q][row] = pad_[mi][h];
                }
            }
        }
        __syncthreads();
        if (tid < BM) {
            int row = tid;
            int grow = bm + row;
            if (grow < M) {
                if constexpr (NHEADS == 1) {
                    as_out[grow] = sAs[0][row] + sAs[1][row] + sAs[2][row] + sAs[3][row];
                    ad_out[grow] = sAd[0][row] + sAd[1][row] + sAd[2][row] + sAd[3][row];
                } else {
                    int h0 = blockIdx.x * 2;
                    as_out[(size_t)grow * 4 + h0]     = sAs[0][row] + sAs[1][row];
                    as_out[(size_t)grow * 4 + h0 + 1] = sAs[2][row] + sAs[3][row];
                    ad_out[(size_t)grow * 4 + h0]     = sAd[0][row] + sAd[1][row];
                    ad_out[(size_t)grow * 4 + h0 + 1] = sAd[2][row] + sAd[3][row];
                }
            }
        }
    }
}

// ============================================================================
// layer-1 aggregation: TWO warps per dst node (parity-split edge list),
// single-pass unnormalized softmax; fp16 gather in, fp16 out.
// Block = 256 threads = 8 warps = 4 nodes.
// ============================================================================
__global__ __launch_bounds__(256) void aggregate_l1(
    const int* __restrict__ off, const int* __restrict__ csr,
    const float* __restrict__ as_, const float* __restrict__ ad_,
    const __half* __restrict__ hh, const float* __restrict__ b1,
    __half* __restrict__ out, int n)
{
    __shared__ float sm[4][32][9];   // [node-in-block][lane][8 acc + dsum]
    int tid = threadIdx.x;
    int warp = tid >> 5, lane = tid & 31;
    int nodeL = warp >> 1, half = warp & 1;
    int gw = blockIdx.x * 4 + nodeL;
    bool valid = gw < n;

    int hd = lane >> 3;
    float adh = 0.f;
    int start = 0, end = 0;
    if (valid) {
        start = off[gw];
        end = off[gw + 1];
        float4 adv = *(const float4*)(ad_ + (size_t)gw * 4);
        adh = (hd == 0) ? adv.x : (hd == 1) ? adv.y : (hd == 2) ? adv.z : adv.w;
    }

    float acc[8];
#pragma unroll
    for (int j = 0; j < 8; j++) acc[j] = 0.f;
    float dsum = 0.f;

    const uint4* hp = (const uint4*)hh;
    int e = start + half;
    for (; e + 6 < end; e += 8) {          // 4 edges of this half (stride 2)
        int s0 = csr[e], s1 = csr[e + 2], s2 = csr[e + 4], s3 = csr[e + 6];
        uint4 p0 = hp[(size_t)s0 * 32 + lane];
        uint4 p1 = hp[(size_t)s1 * 32 + lane];
        uint4 p2 = hp[(size_t)s2 * 32 + lane];
        uint4 p3 = hp[(size_t)s3 * 32 + lane];
        float w0 = __expf(lrelu(as_[(size_t)s0 * 4 + hd] + adh));
        float w1 = __expf(lrelu(as_[(size_t)s1 * 4 + hd] + adh));
        float w2 = __expf(lrelu(as_[(size_t)s2 * 4 + hd] + adh));
        float w3 = __expf(lrelu(as_[(size_t)s3 * 4 + hd] + adh));
        dsum += (w0 + w1) + (w2 + w3);
        h2fma(p0.x, w0, acc[0], acc[1]); h2fma(p0.y, w0, acc[2], acc[3]);
        h2fma(p0.z, w0, acc[4], acc[5]); h2fma(p0.w, w0, acc[6], acc[7]);
        h2fma(p1.x, w1, acc[0], acc[1]); h2fma(p1.y, w1, acc[2], acc[3]);
        h2fma(p1.z, w1, acc[4], acc[5]); h2fma(p1.w, w1, acc[6], acc[7]);
        h2fma(p2.x, w2, acc[0], acc[1]); h2fma(p2.y, w2, acc[2], acc[3]);
        h2fma(p2.z, w2, acc[4], acc[5]); h2fma(p2.w, w2, acc[6], acc[7]);
        h2fma(p3.x, w3, acc[0], acc[1]); h2fma(p3.y, w3, acc[2], acc[3]);
        h2fma(p3.z, w3, acc[4], acc[5]); h2fma(p3.w, w3, acc[6], acc[7]);
    }
    for (; e < end; e += 2) {
        int s0 = csr[e];
        uint4 p0 = hp[(size_t)s0 * 32 + lane];
        float w0 = __expf(lrelu(as_[(size_t)s0 * 4 + hd] + adh));
        dsum += w0;
        h2fma(p0.x, w0, acc[0], acc[1]); h2fma(p0.y, w0, acc[2], acc[3]);
        h2fma(p0.z, w0, acc[4], acc[5]); h2fma(p0.w, w0, acc[6], acc[7]);
    }

    if (half == 1) {
#pragma unroll
        for (int j = 0; j < 8; j++) sm[nodeL][lane][j] = acc[j];
        sm[nodeL][lane][8] = dsum;
    }
    __syncthreads();
    if (half == 0 && valid) {
#pragma unroll
        for (int j = 0; j < 8; j++) acc[j] += sm[nodeL][lane][j];
        dsum += sm[nodeL][lane][8];

        float rh = 1.f / (dsum + 1e-16f);
        float4 bb0 = *(const float4*)(b1 + lane * 8);
        float4 bb1 = *(const float4*)(b1 + lane * 8 + 4);
        float o0 = fmaxf(fmaf(acc[0], rh, bb0.x), 0.f);
        float o1 = fmaxf(fmaf(acc[1], rh, bb0.y), 0.f);
        float o2 = fmaxf(fmaf(acc[2], rh, bb0.z), 0.f);
        float o3 = fmaxf(fmaf(acc[3], rh, bb0.w), 0.f);
        float o4 = fmaxf(fmaf(acc[4], rh, bb1.x), 0.f);
        float o5 = fmaxf(fmaf(acc[5], rh, bb1.y), 0.f);
        float o6 = fmaxf(fmaf(acc[6], rh, bb1.z), 0.f);
        float o7 = fmaxf(fmaf(acc[7], rh, bb1.w), 0.f);
        __half2 q0 = __floats2half2_rn(o0, o1);
        __half2 q1 = __floats2half2_rn(o2, o3);
        __half2 q2 = __floats2half2_rn(o4, o5);
        __half2 q3 = __floats2half2_rn(o6, o7);
        uint4 st;
        st.x = *(uint32_t*)&q0; st.y = *(uint32_t*)&q1;
        st.z = *(uint32_t*)&q2; st.w = *(uint32_t*)&q3;
        *(uint4*)(out + (size_t)gw * 256 + lane * 8) = st;
    }
}

// ============================================================================
// layer-2 aggregation: TWO warps per dst node, single-pass, fp16 gather.
// Block = 256 threads = 4 nodes.
// ============================================================================
__global__ __launch_bounds__(256) void aggregate_l2(
    const int* __restrict__ off, const int* __restrict__ csr,
    const float* __restrict__ as_, const float* __restrict__ ad_,
    const __half* __restrict__ hh, const float* __restrict__ b2,
    float* __restrict__ out, int n)
{
    __shared__ float sm[4][32][5];   // [node-in-block][lane][4 acc + dsum]
    int tid = threadIdx.x;
    int warp = tid >> 5, lane = tid & 31;
    int nodeL = warp >> 1, half = warp & 1;
    int gw = blockIdx.x * 4 + nodeL;
    bool valid = gw < n;

    float adn = 0.f;
    int start = 0, end = 0;
    if (valid) {
        start = off[gw];
        end = off[gw + 1];
        adn = ad_[gw];
    }

    float acc[4] = {0.f, 0.f, 0.f, 0.f};
    float dsum = 0.f;

    const uint2* hp = (const uint2*)hh;
    int e = start + half;
    for (; e + 6 < end; e += 8) {
        int s0 = csr[e], s1 = csr[e + 2], s2 = csr[e + 4], s3 = csr[e + 6];
        uint2 p0 = hp[(size_t)s0 * 32 + lane];
        uint2 p1 = hp[(size_t)s1 * 32 + lane];
        uint2 p2 = hp[(size_t)s2 * 32 + lane];
        uint2 p3 = hp[(size_t)s3 * 32 + lane];
        float w0 = __expf(lrelu(as_[s0] + adn));
        float w1 = __expf(lrelu(as_[s1] + adn));
        float w2 = __expf(lrelu(as_[s2] + adn));
        float w3 = __expf(lrelu(as_[s3] + adn));
        dsum += (w0 + w1) + (w2 + w3);
        h2fma(p0.x, w0, acc[0], acc[1]); h2fma(p0.y, w0, acc[2], acc[3]);
        h2fma(p1.x, w1, acc[0], acc[1]); h2fma(p1.y, w1, acc[2], acc[3]);
        h2fma(p2.x, w2, acc[0], acc[1]); h2fma(p2.y, w2, acc[2], acc[3]);
        h2fma(p3.x, w3, acc[0], acc[1]); h2fma(p3.y, w3, acc[2], acc[3]);
    }
    for (; e < end; e += 2) {
        int s0 = csr[e];
        uint2 p0 = hp[(size_t)s0 * 32 + lane];
        float w0 = __expf(lrelu(as_[s0] + adn));
        dsum += w0;
        h2fma(p0.x, w0, acc[0], acc[1]); h2fma(p0.y, w0, acc[2], acc[3]);
    }

    if (half == 1) {
#pragma unroll
        for (int j = 0; j < 4; j++) sm[nodeL][lane][j] = acc[j];
        sm[nodeL][lane][4] = dsum;
    }
    __syncthreads();
    if (half == 0 && valid) {
#pragma unroll
        for (int j = 0; j < 4; j++) acc[j] += sm[nodeL][lane][j];
        dsum += sm[nodeL][lane][4];

        float r = 1.f / (dsum + 1e-16f);
        float4 bb = *(const float4*)(b2 + lane * 4);
        float4 o = make_float4(fmaf(acc[0], r, bb.x), fmaf(acc[1], r, bb.y),
                               fmaf(acc[2], r, bb.z), fmaf(acc[3], r, bb.w));
        *(float4*)(out + (size_t)gw * OUTC + lane * 4) = o;
    }
}

// ============================================================================
extern "C" void kernel_launch(void* const* d_in, const int* in_sizes, int n_in,
                              void* d_out, int out_size)
{
    const float* x      = (const float*)d_in[0];
    const int*   ei     = (const int*)  d_in[1];
    const float* W1     = (const float*)d_in[2];
    const float* a_src1 = (const float*)d_in[3];
    const float* a_dst1 = (const float*)d_in[4];
    const float* b1     = (const float*)d_in[5];
    const float* W2     = (const float*)d_in[6];
    const float* a_src2 = (const float*)d_in[7];
    const float* a_dst2 = (const float*)d_in[8];
    const float* b2     = (const float*)d_in[9];
    float* out = (float*)d_out;

    int n    = in_sizes[0] / INF_;   // 50000
    int E    = in_sizes[1] / 2;      // 800000
    int Etot = E + n;

    float *as1, *ad1, *as2, *ad2;
    __half *h1h, *out1h, *h2h;
    int *cnt, *off, *part, *csr;
    cudaGetSymbolAddress((void**)&h1h,  g_h1h);
    cudaGetSymbolAddress((void**)&out1h,g_out1h);
    cudaGetSymbolAddress((void**)&as1,  g_as1);
    cudaGetSymbolAddress((void**)&ad1,  g_ad1);
    cudaGetSymbolAddress((void**)&h2h,  g_h2h);
    cudaGetSymbolAddress((void**)&as2,  g_as2);
    cudaGetSymbolAddress((void**)&ad2,  g_ad2);
    cudaGetSymbolAddress((void**)&cnt,  g_cnt);
    cudaGetSymbolAddress((void**)&off,  g_off);
    cudaGetSymbolAddress((void**)&part, g_part);
    cudaGetSymbolAddress((void**)&csr,  g_csr);

    // side stream + fork/join events (created once; host-side handles only)
    static cudaStream_t sB = nullptr;
    static cudaEvent_t  evF = nullptr, evJ = nullptr;
    if (sB == nullptr) {
        cudaStreamCreateWithFlags(&sB, cudaStreamNonBlocking);
        cudaEventCreateWithFlags(&evF, cudaEventDisableTiming);
        cudaEventCreateWithFlags(&evJ, cudaEventDisableTiming);
    }

    const int T = 256;
    auto cdiv = [](int a, int b) { return (a + b - 1) / b; };
    int nchunks = cdiv(n, 1024);

    // ---- fork: CSR build on side stream ----
    cudaEventRecord(evF, 0);
    cudaStreamWaitEvent(sB, evF, 0);

    cudaMemsetAsync(cnt, 0, (size_t)n * sizeof(int), sB);
    count_kernel<<<cdiv(Etot, T * 4), T, 0, sB>>>(ei, E, Etot, cnt);
    scan1_kernel<<<nchunks, 1024, 0, sB>>>(cnt, off, part, n);
    scan_fix_kernel<<<nchunks, 1024, 0, sB>>>(off, cnt, part, n);
    scatter_kernel<<<cdiv(Etot, T * 4), T, 0, sB>>>(ei, E, Etot, cnt, csr);
    cudaEventRecord(evJ, sB);

    // ---- main stream: layer-1 GEMM with fused attn coefficients ----
    {
        dim3 grid(cdiv(HEADS * HID, BN), cdiv(n, BM));
        gemmbf3_kernel<float, 2><<<grid, 256>>>(x, W1, h1h,
                                                a_src1, a_dst1, as1, ad1,
                                                n, HEADS * HID, INF_);
    }

    // ---- join: aggregation needs CSR + alphas + h1h ----
    cudaStreamWaitEvent(0, evJ, 0);
    aggregate_l1<<<cdiv(n, 4), T>>>(off, csr, as1, ad1, h1h, b1, out1h, n);

    // ---- layer 2: fp16-A GEMM with fused attn coefficients, then aggregate ----
    {
        dim3 grid(cdiv(OUTC, BN), cdiv(n, BM));
        gemmbf3_kernel<__half, 1><<<grid, 256>>>(out1h, W2, h2h,
                                                 a_src2, a_dst2, as2, ad2,
                                                 n, OUTC, HEADS * HID);
    }
    aggregate_l2<<<cdiv(n, 4), T>>>(off, csr, as2, ad2, h2h, b2, out, n);
}

// round 14
// speedup vs baseline: 1.0525x; 1.0525x over previous
#include <cuda_runtime.h>
#include <cuda_fp16.h>
#include <cuda_bf16.h>
#include <cstdint>
#include <math.h>

// Problem constants (match reference setup_inputs)
#define NN    50000
#define EE    800000
#define INF_  128
#define HID   64
#define OUTC  128
#define HEADS 4
#define SLOPE 0.2f

#define ETOT (EE + NN)

// ---------------- static device scratch (no allocs allowed) ----------------
__device__ __align__(16) __half g_h1h  [NN * HEADS * HID];  // fp16 h1 (gather)
__device__ __align__(16) __half g_out1h[NN * HEADS * HID];  // fp16 relu(agg+b1)
__device__ __align__(16) float  g_as1 [NN * HEADS];
__device__ __align__(16) float  g_ad1 [NN * HEADS];
__device__ __align__(16) __half g_h2h [NN * OUTC];          // fp16 h2 (gather)
__device__ __align__(16) float  g_as2 [NN];
__device__ __align__(16) float  g_ad2 [NN];

__device__ __align__(16) int   g_cnt [NN];      // degree counts / scatter cursor
__device__ __align__(16) int   g_off [NN + 1];  // CSR row offsets (by dst)
__device__ __align__(16) int   g_part[64];      // per-block totals from scan1
__device__ __align__(16) int   g_csr [ETOT];    // src node per CSR-sorted edge

// ---------------- helpers ----------------
__device__ __forceinline__ float lrelu(float x) { return x >= 0.f ? x : SLOPE * x; }

__device__ __forceinline__ uint32_t pack2bf(float a, float b) {
    __nv_bfloat162 p = __floats2bfloat162_rn(a, b);
    return *reinterpret_cast<uint32_t*>(&p);
}
__device__ __forceinline__ float bf_res(float x) {
    __nv_bfloat16 h = __float2bfloat16(x);
    return x - __bfloat162float(h);
}

__device__ __forceinline__ void h2fma(uint32_t u, float w, float& a, float& b) {
    __half2 h = *(__half2*)&u;
    float2 f = __half22float2(h);
    a = fmaf(f.x, w, a);
    b = fmaf(f.y, w, b);
}

#define MMA_BF16(c, a0, a1, a2, a3, b0, b1)                                  \
    asm volatile("mma.sync.aligned.m16n8k16.row.col.f32.bf16.bf16.f32 "      \
                 "{%0,%1,%2,%3}, {%4,%5,%6,%7}, {%8,%9}, {%0,%1,%2,%3};"     \
                 : "+f"(c[0]), "+f"(c[1]), "+f"(c[2]), "+f"(c[3])            \
                 : "r"(a0), "r"(a1), "r"(a2), "r"(a3), "r"(b0), "r"(b1))

// ============================================================================
// CSR build (runs on side stream sB), 4 edges/thread for atomic MLP
// ============================================================================
__global__ void count_kernel(const int* __restrict__ ei, int E, int Etot,
                             int* __restrict__ cnt) {
    int base = (blockIdx.x * blockDim.x + threadIdx.x) * 4;
    if (base >= Etot) return;
    if (base + 4 <= E && (E & 3) == 0) {
        int4 d4 = *(const int4*)(ei + E + base);
        atomicAdd(cnt + d4.x, 1);
        atomicAdd(cnt + d4.y, 1);
        atomicAdd(cnt + d4.z, 1);
        atomicAdd(cnt + d4.w, 1);
    } else {
#pragma unroll
        for (int j = 0; j < 4; j++) {
            int e = base + j;
            if (e < Etot) {
                int d = (e < E) ? ei[E + e] : (e - E);
                atomicAdd(cnt + d, 1);
            }
        }
    }
}

__global__ void scan1_kernel(const int* __restrict__ cnt, int* __restrict__ off,
                             int* __restrict__ part, int n) {
    __shared__ int wsum[32];
    int tid = threadIdx.x;
    int i = blockIdx.x * 1024 + tid;
    int lane = tid & 31, w = tid >> 5;
    int v = (i < n) ? cnt[i] : 0;
    int x = v;
#pragma unroll
    for (int o = 1; o < 32; o <<= 1) {
        int y = __shfl_up_sync(0xffffffffu, x, o);
        if (lane >= o) x += y;
    }
    if (lane == 31) wsum[w] = x;
    __syncthreads();
    if (w == 0) {
        int s = wsum[lane];
#pragma unroll
        for (int o = 1; o < 32; o <<= 1) {
            int y = __shfl_up_sync(0xffffffffu, s, o);
            if (lane >= o) s += y;
        }
        wsum[lane] = s;
    }
    __syncthreads();
    int incl = x + (w > 0 ? wsum[w - 1] : 0);
    if (i < n) off[i + 1] = incl;
    if (tid == 1023) part[blockIdx.x] = incl;
}

__global__ void scan_fix_kernel(int* __restrict__ off, int* __restrict__ cnt,
                                const int* __restrict__ part, int n) {
    __shared__ int wsum2[2];
    __shared__ int base_s;
    int b = blockIdx.x;
    int tid = threadIdx.x;
    if (tid < 64) {
        int v = (tid < b) ? part[tid] : 0;
#pragma unroll
        for (int o = 16; o; o >>= 1) v += __shfl_xor_sync(0xffffffffu, v, o);
        if ((tid & 31) == 0) wsum2[tid >> 5] = v;
    }
    __syncthreads();
    if (tid == 0) base_s = wsum2[0] + wsum2[1];
    __syncthreads();
    int base = base_s;
    int i = b * 1024 + tid;
    if (b == 0 && tid == 0) { off[0] = 0; cnt[0] = 0; }
    if (i < n) {
        int o = off[i + 1] + base;
        off[i + 1] = o;
        if (i + 1 < n) cnt[i + 1] = o;
    }
}

__global__ void scatter_kernel(const int* __restrict__ ei, int E, int Etot,
                               int* __restrict__ cur, int* __restrict__ csr) {
    int base = (blockIdx.x * blockDim.x + threadIdx.x) * 4;
    if (base >= Etot) return;
    if (base + 4 <= E && (E & 3) == 0) {
        int4 s4 = *(const int4*)(ei + base);
        int4 d4 = *(const int4*)(ei + E + base);
        int p0 = atomicAdd(cur + d4.x, 1);
        int p1 = atomicAdd(cur + d4.y, 1);
        int p2 = atomicAdd(cur + d4.z, 1);
        int p3 = atomicAdd(cur + d4.w, 1);
        csr[p0] = s4.x; csr[p1] = s4.y; csr[p2] = s4.z; csr[p3] = s4.w;
    } else {
#pragma unroll
        for (int j = 0; j < 4; j++) {
            int e = base + j;
            if (e < Etot) {
                int s, d;
                if (e < E) { s = ei[e]; d = ei[E + e]; } else { s = e - E; d = s; }
                int pos = atomicAdd(cur + d, 1);
                csr[pos] = s;
            }
        }
    }
}

// ============================================================================
// 3xBF16 tensor-core GEMM, fp16 output, fused attention-coefficient epilogue.
// AT: fp32 or fp16 A operand. NHEADS: heads covered per block (BN=128):
//   1 -> as_out[row] = C_row(block cols) . av   (layer 2, N=128)
//   2 -> block cols split at 64; as_out[row*4 + bx*2 + bin]   (layer 1, N=256)
// ============================================================================
#define BM 128
#define BN 128
#define BK 16
#define AST 12
#define BST 13

template <typename AT, int NHEADS>
__global__ __launch_bounds__(256) void gemmbf3_kernel(
    const AT* __restrict__ A, const float* __restrict__ B,
    __half* __restrict__ Ch,
    const float* __restrict__ av_src, const float* __restrict__ av_dst,
    float* __restrict__ as_out, float* __restrict__ ad_out,
    int M, int N, int K)
{
    __shared__ uint32_t Ah[BM * AST], Al[BM * AST];
    __shared__ uint32_t Bh[BN * BST], Bl[BN * BST];
    __shared__ float sAs[4][BM], sAd[4][BM];

    int tid  = threadIdx.x;
    int bm   = blockIdx.y * BM;
    int bn   = blockIdx.x * BN;
    int warp = tid >> 5, lane = tid & 31;
    int wm = (warp & 1) * 64;
    int wn = (warp >> 1) * 32;
    int g = lane >> 2, t = lane & 3;

    float acc[4][4][4];
#pragma unroll
    for (int mi = 0; mi < 4; mi++)
#pragma unroll
        for (int ni = 0; ni < 4; ni++)
#pragma unroll
            for (int j = 0; j < 4; j++) acc[mi][ni][j] = 0.f;

    float4 ra[2], rb0, rb1;
    int c0 = (tid & 31) * 4;
    int kp = tid >> 5;

    auto loadTiles = [&](int kt) {
#pragma unroll
        for (int t2 = 0; t2 < 2; t2++) {
            int f = tid + t2 * 256;
            int r = f >> 2, kc = (f & 3) * 4;
            int row = bm + r;
            if (row < M) {
                if constexpr (sizeof(AT) == 4) {
                    ra[t2] = *(const float4*)((const float*)A + (size_t)row * K + kt + kc);
                } else {
                    uint2 u = *(const uint2*)((const __half*)A + (size_t)row * K + kt + kc);
                    float2 f0 = __half22float2(*(__half2*)&u.x);
                    float2 f1 = __half22float2(*(__half2*)&u.y);
                    ra[t2] = make_float4(f0.x, f0.y, f1.x, f1.y);
                }
            } else {
                ra[t2] = make_float4(0.f, 0.f, 0.f, 0.f);
            }
        }
        rb0 = *(const float4*)(B + (size_t)(kt + 2 * kp) * N + bn + c0);
        rb1 = *(const float4*)(B + (size_t)(kt + 2 * kp + 1) * N + bn + c0);
    };

    auto storeTiles = [&]() {
#pragma unroll
        for (int t2 = 0; t2 < 2; t2++) {
            int f = tid + t2 * 256;
            int r = f >> 2, kc = (f & 3) * 4;
            float v0 = (&ra[t2].x)[0], v1 = (&ra[t2].x)[1];
            float v2 = (&ra[t2].x)[2], v3 = (&ra[t2].x)[3];
            int w = r * AST + (kc >> 1);
            Ah[w]     = pack2bf(v0, v1);
            Ah[w + 1] = pack2bf(v2, v3);
            Al[w]     = pack2bf(bf_res(v0), bf_res(v1));
            Al[w + 1] = pack2bf(bf_res(v2), bf_res(v3));
        }
        float q0[4] = {rb0.x, rb0.y, rb0.z, rb0.w};
        float q1[4] = {rb1.x, rb1.y, rb1.z, rb1.w};
#pragma unroll
        for (int j = 0; j < 4; j++) {
            Bh[(c0 + j) * BST + kp] = pack2bf(q0[j], q1[j]);
            Bl[(c0 + j) * BST + kp] = pack2bf(bf_res(q0[j]), bf_res(q1[j]));
        }
    };

    loadTiles(0);
    storeTiles();
    __syncthreads();

    for (int kt = 0; kt < K; kt += BK) {
        bool nx = (kt + BK) < K;
        if (nx) loadTiles(kt + BK);

        uint32_t bh0[4], bh1[4], bl0[4], bl1[4];
#pragma unroll
        for (int ni = 0; ni < 4; ni++) {
            int cw = (wn + ni * 8 + g) * BST;
            bh0[ni] = Bh[cw + t]; bh1[ni] = Bh[cw + 4 + t];
            bl0[ni] = Bl[cw + t]; bl1[ni] = Bl[cw + 4 + t];
        }
#pragma unroll
        for (int mi = 0; mi < 4; mi++) {
            int r0w = (wm + mi * 16 + g) * AST;
            int r1w = r0w + 8 * AST;
            uint32_t ah0 = Ah[r0w + t],     ah1 = Ah[r1w + t];
            uint32_t ah2 = Ah[r0w + 4 + t], ah3 = Ah[r1w + 4 + t];
            uint32_t al0 = Al[r0w + t],     al1 = Al[r1w + t];
            uint32_t al2 = Al[r0w + 4 + t], al3 = Al[r1w + 4 + t];
#pragma unroll
            for (int ni = 0; ni < 4; ni++) {
                MMA_BF16(acc[mi][ni], ah0, ah1, ah2, ah3, bh0[ni], bh1[ni]);
                MMA_BF16(acc[mi][ni], ah0, ah1, ah2, ah3, bl0[ni], bl1[ni]);
                MMA_BF16(acc[mi][ni], al0, al1, al2, al3, bh0[ni], bh1[ni]);
            }
        }
        __syncthreads();
        if (nx) {
            storeTiles();
        }
        __syncthreads();
    }

    // ---- epilogue: fp16 store ----
#pragma unroll
    for (int mi = 0; mi < 4; mi++) {
#pragma unroll
        for (int ni = 0; ni < 4; ni++) {
            int row = bm + wm + mi * 16 + g;
            int col = bn + wn + ni * 8 + 2 * t;
            if (row < M)
                *(__half2*)(Ch + (size_t)row * N + col) =
                    __floats2half2_rn(acc[mi][ni][0], acc[mi][ni][1]);
            if (row + 8 < M)
                *(__half2*)(Ch + (size_t)(row + 8) * N + col) =
                    __floats2half2_rn(acc[mi][ni][2], acc[mi][ni][3]);
        }
    }

    // ---- fused attention-coefficient epilogue ----
    {
        float pas[4][2] = {{0.f,0.f},{0.f,0.f},{0.f,0.f},{0.f,0.f}};
        float pad_[4][2] = {{0.f,0.f},{0.f,0.f},{0.f,0.f},{0.f,0.f}};
#pragma unroll
        for (int ni = 0; ni < 4; ni++) {
#pragma unroll
            for (int j2 = 0; j2 < 2; j2++) {
                int colL = wn + ni * 8 + 2 * t + j2;
                float a = av_src[bn + colL];
                float b = av_dst[bn + colL];
#pragma unroll
                for (int mi = 0; mi < 4; mi++) {
                    pas[mi][0] = fmaf(acc[mi][ni][j2],     a, pas[mi][0]);
                    pas[mi][1] = fmaf(acc[mi][ni][2 + j2], a, pas[mi][1]);
                    pad_[mi][0] = fmaf(acc[mi][ni][j2],     b, pad_[mi][0]);
                    pad_[mi][1] = fmaf(acc[mi][ni][2 + j2], b, pad_[mi][1]);
                }
            }
        }
#pragma unroll
        for (int off = 1; off < 4; off <<= 1) {
#pragma unroll
            for (int mi = 0; mi < 4; mi++) {
#pragma unroll
                for (int h = 0; h < 2; h++) {
                    pas[mi][h] += __shfl_xor_sync(0xffffffffu, pas[mi][h], off);
                    pad_[mi][h] += __shfl_xor_sync(0xffffffffu, pad_[mi][h], off);
                }
            }
        }
        if (t == 0) {
            int q = warp >> 1;   // = wn/32; rows disjoint between warp pairs
#pragma unroll
            for (int mi = 0; mi < 4; mi++) {
#pragma unroll
                for (int h = 0; h < 2; h++) {
                    int row = wm + mi * 16 + h * 8 + g;
                    sAs[q][row] = pas[mi][h];
                    sAd[q][row] = pad_[mi][h];
                }
            }
        }
        __syncthreads();
        if (tid < BM) {
            int row = tid;
            int grow = bm + row;
            if (grow < M) {
                if constexpr (NHEADS == 1) {
                    as_out[grow] = sAs[0][row] + sAs[1][row] + sAs[2][row] + sAs[3][row];
                    ad_out[grow] = sAd[0][row] + sAd[1][row] + sAd[2][row] + sAd[3][row];
                } else {
                    int h0 = blockIdx.x * 2;
                    as_out[(size_t)grow * 4 + h0]     = sAs[0][row] + sAs[1][row];
                    as_out[(size_t)grow * 4 + h0 + 1] = sAs[2][row] + sAs[3][row];
                    ad_out[(size_t)grow * 4 + h0]     = sAd[0][row] + sAd[1][row];
                    ad_out[(size_t)grow * 4 + h0 + 1] = sAd[2][row] + sAd[3][row];
                }
            }
        }
    }
}

// ============================================================================
// layer-1 aggregation: one warp per dst node, single-pass unnormalized
// softmax; fp16 gather in, fp16 out (GEMM2's A operand).
// ============================================================================
__global__ __launch_bounds__(256) void aggregate_l1(
    const int* __restrict__ off, const int* __restrict__ csr,
    const float* __restrict__ as_, const float* __restrict__ ad_,
    const __half* __restrict__ hh, const float* __restrict__ b1,
    __half* __restrict__ out, int n)
{
    int gw = (blockIdx.x * blockDim.x + threadIdx.x) >> 5;
    int lane = threadIdx.x & 31;
    if (gw >= n) return;
    int start = off[gw], end = off[gw + 1];

    float4 adv = *(const float4*)(ad_ + (size_t)gw * 4);
    int hd = lane >> 3;
    float adh = (hd == 0) ? adv.x : (hd == 1) ? adv.y : (hd == 2) ? adv.z : adv.w;

    float acc[8];
#pragma unroll
    for (int j = 0; j < 8; j++) acc[j] = 0.f;
    float dsum = 0.f;

    const uint4* hp = (const uint4*)hh;
    int e = start;
    for (; e + 4 <= end; e += 4) {
        int s0 = csr[e], s1 = csr[e + 1], s2 = csr[e + 2], s3 = csr[e + 3];
        uint4 p0 = hp[(size_t)s0 * 32 + lane];
        uint4 p1 = hp[(size_t)s1 * 32 + lane];
        uint4 p2 = hp[(size_t)s2 * 32 + lane];
        uint4 p3 = hp[(size_t)s3 * 32 + lane];
        float w0 = __expf(lrelu(as_[(size_t)s0 * 4 + hd] + adh));
        float w1 = __expf(lrelu(as_[(size_t)s1 * 4 + hd] + adh));
        float w2 = __expf(lrelu(as_[(size_t)s2 * 4 + hd] + adh));
        float w3 = __expf(lrelu(as_[(size_t)s3 * 4 + hd] + adh));
        dsum += (w0 + w1) + (w2 + w3);
        h2fma(p0.x, w0, acc[0], acc[1]); h2fma(p0.y, w0, acc[2], acc[3]);
        h2fma(p0.z, w0, acc[4], acc[5]); h2fma(p0.w, w0, acc[6], acc[7]);
        h2fma(p1.x, w1, acc[0], acc[1]); h2fma(p1.y, w1, acc[2], acc[3]);
        h2fma(p1.z, w1, acc[4], acc[5]); h2fma(p1.w, w1, acc[6], acc[7]);
        h2fma(p2.x, w2, acc[0], acc[1]); h2fma(p2.y, w2, acc[2], acc[3]);
        h2fma(p2.z, w2, acc[4], acc[5]); h2fma(p2.w, w2, acc[6], acc[7]);
        h2fma(p3.x, w3, acc[0], acc[1]); h2fma(p3.y, w3, acc[2], acc[3]);
        h2fma(p3.z, w3, acc[4], acc[5]); h2fma(p3.w, w3, acc[6], acc[7]);
    }
    for (; e < end; e++) {
        int s0 = csr[e];
        uint4 p0 = hp[(size_t)s0 * 32 + lane];
        float w0 = __expf(lrelu(as_[(size_t)s0 * 4 + hd] + adh));
        dsum += w0;
        h2fma(p0.x, w0, acc[0], acc[1]); h2fma(p0.y, w0, acc[2], acc[3]);
        h2fma(p0.z, w0, acc[4], acc[5]); h2fma(p0.w, w0, acc[6], acc[7]);
    }

    float rh = 1.f / (dsum + 1e-16f);
    float4 bb0 = *(const float4*)(b1 + lane * 8);
    float4 bb1 = *(const float4*)(b1 + lane * 8 + 4);
    float o0 = fmaxf(fmaf(acc[0], rh, bb0.x), 0.f);
    float o1 = fmaxf(fmaf(acc[1], rh, bb0.y), 0.f);
    float o2 = fmaxf(fmaf(acc[2], rh, bb0.z), 0.f);
    float o3 = fmaxf(fmaf(acc[3], rh, bb0.w), 0.f);
    float o4 = fmaxf(fmaf(acc[4], rh, bb1.x), 0.f);
    float o5 = fmaxf(fmaf(acc[5], rh, bb1.y), 0.f);
    float o6 = fmaxf(fmaf(acc[6], rh, bb1.z), 0.f);
    float o7 = fmaxf(fmaf(acc[7], rh, bb1.w), 0.f);
    __half2 q0 = __floats2half2_rn(o0, o1);
    __half2 q1 = __floats2half2_rn(o2, o3);
    __half2 q2 = __floats2half2_rn(o4, o5);
    __half2 q3 = __floats2half2_rn(o6, o7);
    uint4 st;
    st.x = *(uint32_t*)&q0; st.y = *(uint32_t*)&q1;
    st.z = *(uint32_t*)&q2; st.w = *(uint32_t*)&q3;
    *(uint4*)(out + (size_t)gw * 256 + lane * 8) = st;
}

// ============================================================================
// layer-2 aggregation: one warp per dst node, single-pass, fp16 gather.
// ============================================================================
__global__ __launch_bounds__(256) void aggregate_l2(
    const int* __restrict__ off, const int* __restrict__ csr,
    const float* __restrict__ as_, const float* __restrict__ ad_,
    const __half* __restrict__ hh, const float* __restrict__ b2,
    float* __restrict__ out, int n)
{
    int gw = (blockIdx.x * blockDim.x + threadIdx.x) >> 5;
    int lane = threadIdx.x & 31;
    if (gw >= n) return;
    int start = off[gw], end = off[gw + 1];

    float adn = ad_[gw];
    float acc[4] = {0.f, 0.f, 0.f, 0.f};
    float dsum = 0.f;

    const uint2* hp = (const uint2*)hh;
    int e = start;
    for (; e + 4 <= end; e += 4) {
        int s0 = csr[e], s1 = csr[e + 1], s2 = csr[e + 2], s3 = csr[e + 3];
        uint2 p0 = hp[(size_t)s0 * 32 + lane];
        uint2 p1 = hp[(size_t)s1 * 32 + lane];
        uint2 p2 = hp[(size_t)s2 * 32 + lane];
        uint2 p3 = hp[(size_t)s3 * 32 + lane];
        float w0 = __expf(lrelu(as_[s0] + adn));
        float w1 = __expf(lrelu(as_[s1] + adn));
        float w2 = __expf(lrelu(as_[s2] + adn));
        float w3 = __expf(lrelu(as_[s3] + adn));
        dsum += (w0 + w1) + (w2 + w3);
        h2fma(p0.x, w0, acc[0], acc[1]); h2fma(p0.y, w0, acc[2], acc[3]);
        h2fma(p1.x, w1, acc[0], acc[1]); h2fma(p1.y, w1, acc[2], acc[3]);
        h2fma(p2.x, w2, acc[0], acc[1]); h2fma(p2.y, w2, acc[2], acc[3]);
        h2fma(p3.x, w3, acc[0], acc[1]); h2fma(p3.y, w3, acc[2], acc[3]);
    }
    for (; e < end; e++) {
        int s0 = csr[e];
        uint2 p0 = hp[(size_t)s0 * 32 + lane];
        float w0 = __expf(lrelu(as_[s0] + adn));
        dsum += w0;
        h2fma(p0.x, w0, acc[0], acc[1]); h2fma(p0.y, w0, acc[2], acc[3]);
    }

    float r = 1.f / (dsum + 1e-16f);
    float4 bb = *(const float4*)(b2 + lane * 4);
    float4 o = make_float4(fmaf(acc[0], r, bb.x), fmaf(acc[1], r, bb.y),
                           fmaf(acc[2], r, bb.z), fmaf(acc[3], r, bb.w));
    *(float4*)(out + (size_t)gw * OUTC + lane * 4) = o;
}

// ============================================================================
extern "C" void kernel_launch(void* const* d_in, const int* in_sizes, int n_in,
                              void* d_out, int out_size)
{
    const float* x      = (const float*)d_in[0];
    const int*   ei     = (const int*)  d_in[1];
    const float* W1     = (const float*)d_in[2];
    const float* a_src1 = (const float*)d_in[3];
    const float* a_dst1 = (const float*)d_in[4];
    const float* b1     = (const float*)d_in[5];
    const float* W2     = (const float*)d_in[6];
    const float* a_src2 = (const float*)d_in[7];
    const float* a_dst2 = (const float*)d_in[8];
    const float* b2     = (const float*)d_in[9];
    float* out = (float*)d_out;

    int n    = in_sizes[0] / INF_;   // 50000
    int E    = in_sizes[1] / 2;      // 800000
    int Etot = E + n;

    float *as1, *ad1, *as2, *ad2;
    __half *h1h, *out1h, *h2h;
    int *cnt, *off, *part, *csr;
    cudaGetSymbolAddress((void**)&h1h,  g_h1h);
    cudaGetSymbolAddress((void**)&out1h,g_out1h);
    cudaGetSymbolAddress((void**)&as1,  g_as1);
    cudaGetSymbolAddress((void**)&ad1,  g_ad1);
    cudaGetSymbolAddress((void**)&h2h,  g_h2h);
    cudaGetSymbolAddress((void**)&as2,  g_as2);
    cudaGetSymbolAddress((void**)&ad2,  g_ad2);
    cudaGetSymbolAddress((void**)&cnt,  g_cnt);
    cudaGetSymbolAddress((void**)&off,  g_off);
    cudaGetSymbolAddress((void**)&part, g_part);
    cudaGetSymbolAddress((void**)&csr,  g_csr);

    // side stream + fork/join events (created once; host-side handles only)
    static cudaStream_t sB = nullptr;
    static cudaEvent_t  evF = nullptr, evJ = nullptr;
    if (sB == nullptr) {
        cudaStreamCreateWithFlags(&sB, cudaStreamNonBlocking);
        cudaEventCreateWithFlags(&evF, cudaEventDisableTiming);
        cudaEventCreateWithFlags(&evJ, cudaEventDisableTiming);
    }

    const int T = 256;
    auto cdiv = [](int a, int b) { return (a + b - 1) / b; };
    int nchunks = cdiv(n, 1024);

    // ---- fork: CSR build on side stream ----
    cudaEventRecord(evF, 0);
    cudaStreamWaitEvent(sB, evF, 0);

    cudaMemsetAsync(cnt, 0, (size_t)n * sizeof(int), sB);
    count_kernel<<<cdiv(Etot, T * 4), T, 0, sB>>>(ei, E, Etot, cnt);
    scan1_kernel<<<nchunks, 1024, 0, sB>>>(cnt, off, part, n);
    scan_fix_kernel<<<nchunks, 1024, 0, sB>>>(off, cnt, part, n);
    scatter_kernel<<<cdiv(Etot, T * 4), T, 0, sB>>>(ei, E, Etot, cnt, csr);
    cudaEventRecord(evJ, sB);

    // ---- main stream: layer-1 GEMM with fused attn coefficients ----
    {
        dim3 grid(cdiv(HEADS * HID, BN), cdiv(n, BM));
        gemmbf3_kernel<float, 2><<<grid, 256>>>(x, W1, h1h,
                                                a_src1, a_dst1, as1, ad1,
                                                n, HEADS * HID, INF_);
    }

    // ---- join: aggregation needs CSR + alphas + h1h ----
    cudaStreamWaitEvent(0, evJ, 0);
    aggregate_l1<<<cdiv(n * 32, T), T>>>(off, csr, as1, ad1, h1h, b1, out1h, n);

    // ---- layer 2: fp16-A GEMM with fused attn coefficients, then aggregate ----
    {
        dim3 grid(cdiv(OUTC, BN), cdiv(n, BM));
        gemmbf3_kernel<__half, 1><<<grid, 256>>>(out1h, W2, h2h,
                                                 a_src2, a_dst2, as2, ad2,
                                                 n, OUTC, HEADS * HID);
    }
    aggregate_l2<<<cdiv(n * 32, T), T>>>(off, csr, as2, ad2, h2h, b2, out, n);
}

// round 16
// speedup vs baseline: 1.1121x; 1.0566x over previous
#include <cuda_runtime.h>
#include <cuda_fp16.h>
#include <cuda_bf16.h>
#include <cstdint>
#include <math.h>

// Problem constants (match reference setup_inputs)
#define NN    50000
#define EE    800000
#define INF_  128
#define HID   64
#define OUTC  128
#define HEADS 4
#define SLOPE 0.2f

#define ETOT (EE + NN)

// ---------------- static device scratch (no allocs allowed) ----------------
__device__ __align__(16) __half g_h1h  [NN * HEADS * HID];  // fp16 h1 (gather)
__device__ __align__(16) __half g_out1h[NN * HEADS * HID];  // fp16 relu(agg+b1)
__device__ __align__(16) float  g_as1 [NN * HEADS];
__device__ __align__(16) float  g_ad1 [NN * HEADS];
__device__ __align__(16) __half g_h2h [NN * OUTC];          // fp16 h2 (gather)
__device__ __align__(16) float  g_as2 [NN];
__device__ __align__(16) float  g_ad2 [NN];

__device__ __align__(16) int   g_cnt [NN];      // degree counts / scatter cursor
__device__ __align__(16) int   g_off [NN + 1];  // CSR row offsets (by dst)
__device__ __align__(16) int   g_part[64];      // per-block totals from scan1
__device__ __align__(16) int   g_csr [ETOT];    // src node per CSR-sorted edge

// ---------------- helpers ----------------
__device__ __forceinline__ float lrelu(float x) { return x >= 0.f ? x : SLOPE * x; }

__device__ __forceinline__ uint32_t pack2bf(float a, float b) {
    __nv_bfloat162 p = __floats2bfloat162_rn(a, b);
    return *reinterpret_cast<uint32_t*>(&p);
}
__device__ __forceinline__ float bf_res(float x) {
    __nv_bfloat16 h = __float2bfloat16(x);
    return x - __bfloat162float(h);
}
__device__ __forceinline__ uint32_t pack2h(float a, float b) {
    __half2 p = __floats2half2_rn(a, b);
    return *reinterpret_cast<uint32_t*>(&p);
}
__device__ __forceinline__ float h_res(float x) {
    __half h = __float2half_rn(x);
    return x - __half2float(h);
}

__device__ __forceinline__ void h2fma(uint32_t u, float w, float& a, float& b) {
    __half2 h = *(__half2*)&u;
    float2 f = __half22float2(h);
    a = fmaf(f.x, w, a);
    b = fmaf(f.y, w, b);
}

#define MMA_BF16(c, a0, a1, a2, a3, b0, b1)                                  \
    asm volatile("mma.sync.aligned.m16n8k16.row.col.f32.bf16.bf16.f32 "      \
                 "{%0,%1,%2,%3}, {%4,%5,%6,%7}, {%8,%9}, {%0,%1,%2,%3};"     \
                 : "+f"(c[0]), "+f"(c[1]), "+f"(c[2]), "+f"(c[3])            \
                 : "r"(a0), "r"(a1), "r"(a2), "r"(a3), "r"(b0), "r"(b1))

#define MMA_F16(c, a0, a1, a2, a3, b0, b1)                                   \
    asm volatile("mma.sync.aligned.m16n8k16.row.col.f32.f16.f16.f32 "        \
                 "{%0,%1,%2,%3}, {%4,%5,%6,%7}, {%8,%9}, {%0,%1,%2,%3};"     \
                 : "+f"(c[0]), "+f"(c[1]), "+f"(c[2]), "+f"(c[3])            \
                 : "r"(a0), "r"(a1), "r"(a2), "r"(a3), "r"(b0), "r"(b1))

// ============================================================================
// CSR build (runs on side stream sB), 4 edges/thread for atomic MLP
// ============================================================================
__global__ void count_kernel(const int* __restrict__ ei, int E, int Etot,
                             int* __restrict__ cnt) {
    int base = (blockIdx.x * blockDim.x + threadIdx.x) * 4;
    if (base >= Etot) return;
    if (base + 4 <= E && (E & 3) == 0) {
        int4 d4 = *(const int4*)(ei + E + base);
        atomicAdd(cnt + d4.x, 1);
        atomicAdd(cnt + d4.y, 1);
        atomicAdd(cnt + d4.z, 1);
        atomicAdd(cnt + d4.w, 1);
    } else {
#pragma unroll
        for (int j = 0; j < 4; j++) {
            int e = base + j;
            if (e < Etot) {
                int d = (e < E) ? ei[E + e] : (e - E);
                atomicAdd(cnt + d, 1);
            }
        }
    }
}

__global__ void scan1_kernel(const int* __restrict__ cnt, int* __restrict__ off,
                             int* __restrict__ part, int n) {
    __shared__ int wsum[32];
    int tid = threadIdx.x;
    int i = blockIdx.x * 1024 + tid;
    int lane = tid & 31, w = tid >> 5;
    int v = (i < n) ? cnt[i] : 0;
    int x = v;
#pragma unroll
    for (int o = 1; o < 32; o <<= 1) {
        int y = __shfl_up_sync(0xffffffffu, x, o);
        if (lane >= o) x += y;
    }
    if (lane == 31) wsum[w] = x;
    __syncthreads();
    if (w == 0) {
        int s = wsum[lane];
#pragma unroll
        for (int o = 1; o < 32; o <<= 1) {
            int y = __shfl_up_sync(0xffffffffu, s, o);
            if (lane >= o) s += y;
        }
        wsum[lane] = s;
    }
    __syncthreads();
    int incl = x + (w > 0 ? wsum[w - 1] : 0);
    if (i < n) off[i + 1] = incl;
    if (tid == 1023) part[blockIdx.x] = incl;
}

__global__ void scan_fix_kernel(int* __restrict__ off, int* __restrict__ cnt,
                                const int* __restrict__ part, int n) {
    __shared__ int wsum2[2];
    __shared__ int base_s;
    int b = blockIdx.x;
    int tid = threadIdx.x;
    if (tid < 64) {
        int v = (tid < b) ? part[tid] : 0;
#pragma unroll
        for (int o = 16; o; o >>= 1) v += __shfl_xor_sync(0xffffffffu, v, o);
        if ((tid & 31) == 0) wsum2[tid >> 5] = v;
    }
    __syncthreads();
    if (tid == 0) base_s = wsum2[0] + wsum2[1];
    __syncthreads();
    int base = base_s;
    int i = b * 1024 + tid;
    if (b == 0 && tid == 0) { off[0] = 0; cnt[0] = 0; }
    if (i < n) {
        int o = off[i + 1] + base;
        off[i + 1] = o;
        if (i + 1 < n) cnt[i + 1] = o;
    }
}

__global__ void scatter_kernel(const int* __restrict__ ei, int E, int Etot,
                               int* __restrict__ cur, int* __restrict__ csr) {
    int base = (blockIdx.x * blockDim.x + threadIdx.x) * 4;
    if (base >= Etot) return;
    if (base + 4 <= E && (E & 3) == 0) {
        int4 s4 = *(const int4*)(ei + base);
        int4 d4 = *(const int4*)(ei + E + base);
        int p0 = atomicAdd(cur + d4.x, 1);
        int p1 = atomicAdd(cur + d4.y, 1);
        int p2 = atomicAdd(cur + d4.z, 1);
        int p3 = atomicAdd(cur + d4.w, 1);
        csr[p0] = s4.x; csr[p1] = s4.y; csr[p2] = s4.z; csr[p3] = s4.w;
    } else {
#pragma unroll
        for (int j = 0; j < 4; j++) {
            int e = base + j;
            if (e < Etot) {
                int s, d;
                if (e < E) { s = ei[e]; d = ei[E + e]; } else { s = e - E; d = s; }
                int pos = atomicAdd(cur + d, 1);
                csr[pos] = s;
            }
        }
    }
}

// ============================================================================
// Tensor-core GEMM, fp16 output, fused attention-coefficient epilogue.
// AT=float : 3-term bf16 split (hi/lo) — fp32-class accuracy.
// AT=__half: A is EXACT in fp16 -> f16 MMA, 2 terms (A*Bhi + A*Blo).
// NHEADS: heads covered per block (BN=128):
//   1 -> as_out[row] = C_row(block cols) . av   (layer 2, N=128)
//   2 -> block cols split at 64; as_out[row*4 + bx*2 + bin]   (layer 1, N=256)
// ============================================================================
#define BM 128
#define BN 128
#define BK 16
#define AST 12
#define BST 13

template <typename AT, int NHEADS>
__global__ __launch_bounds__(256) void gemmbf3_kernel(
    const AT* __restrict__ A, const float* __restrict__ B,
    __half* __restrict__ Ch,
    const float* __restrict__ av_src, const float* __restrict__ av_dst,
    float* __restrict__ as_out, float* __restrict__ ad_out,
    int M, int N, int K)
{
    constexpr bool F16MODE = (sizeof(AT) == 2);

    __shared__ uint32_t Ah[BM * AST], Al[BM * AST];   // Al unused in F16 mode
    __shared__ uint32_t Bh[BN * BST], Bl[BN * BST];
    __shared__ float sAs[4][BM], sAd[4][BM];

    int tid  = threadIdx.x;
    int bm   = blockIdx.y * BM;
    int bn   = blockIdx.x * BN;
    int warp = tid >> 5, lane = tid & 31;
    int wm = (warp & 1) * 64;
    int wn = (warp >> 1) * 32;
    int g = lane >> 2, t = lane & 3;

    float acc[4][4][4];
#pragma unroll
    for (int mi = 0; mi < 4; mi++)
#pragma unroll
        for (int ni = 0; ni < 4; ni++)
#pragma unroll
            for (int j = 0; j < 4; j++) acc[mi][ni][j] = 0.f;

    float4 ra[2], rb0, rb1;
    int c0 = (tid & 31) * 4;
    int kp = tid >> 5;

    auto loadTiles = [&](int kt) {
#pragma unroll
        for (int t2 = 0; t2 < 2; t2++) {
            int f = tid + t2 * 256;
            int r = f >> 2, kc = (f & 3) * 4;
            int row = bm + r;
            if (row < M) {
                if constexpr (!F16MODE) {
                    ra[t2] = *(const float4*)((const float*)A + (size_t)row * K + kt + kc);
                } else {
                    uint2 u = *(const uint2*)((const __half*)A + (size_t)row * K + kt + kc);
                    float2 f0 = __half22float2(*(__half2*)&u.x);
                    float2 f1 = __half22float2(*(__half2*)&u.y);
                    ra[t2] = make_float4(f0.x, f0.y, f1.x, f1.y);
                }
            } else {
                ra[t2] = make_float4(0.f, 0.f, 0.f, 0.f);
            }
        }
        rb0 = *(const float4*)(B + (size_t)(kt + 2 * kp) * N + bn + c0);
        rb1 = *(const float4*)(B + (size_t)(kt + 2 * kp + 1) * N + bn + c0);
    };

    auto storeTiles = [&]() {
#pragma unroll
        for (int t2 = 0; t2 < 2; t2++) {
            int f = tid + t2 * 256;
            int r = f >> 2, kc = (f & 3) * 4;
            float v0 = (&ra[t2].x)[0], v1 = (&ra[t2].x)[1];
            float v2 = (&ra[t2].x)[2], v3 = (&ra[t2].x)[3];
            int w = r * AST + (kc >> 1);
            if constexpr (F16MODE) {
                // A values are exactly fp16-representable (round-trip exact)
                Ah[w]     = pack2h(v0, v1);
                Ah[w + 1] = pack2h(v2, v3);
            } else {
                Ah[w]     = pack2bf(v0, v1);
                Ah[w + 1] = pack2bf(v2, v3);
                Al[w]     = pack2bf(bf_res(v0), bf_res(v1));
                Al[w + 1] = pack2bf(bf_res(v2), bf_res(v3));
            }
        }
        float q0[4] = {rb0.x, rb0.y, rb0.z, rb0.w};
        float q1[4] = {rb1.x, rb1.y, rb1.z, rb1.w};
#pragma unroll
        for (int j = 0; j < 4; j++) {
            if constexpr (F16MODE) {
                Bh[(c0 + j) * BST + kp] = pack2h(q0[j], q1[j]);
                Bl[(c0 + j) * BST + kp] = pack2h(h_res(q0[j]), h_res(q1[j]));
            } else {
                Bh[(c0 + j) * BST + kp] = pack2bf(q0[j], q1[j]);
                Bl[(c0 + j) * BST + kp] = pack2bf(bf_res(q0[j]), bf_res(q1[j]));
            }
        }
    };

    loadTiles(0);
    storeTiles();
    __syncthreads();

    for (int kt = 0; kt < K; kt += BK) {
        bool nx = (kt + BK) < K;
        if (nx) loadTiles(kt + BK);

        uint32_t bh0[4], bh1[4], bl0[4], bl1[4];
#pragma unroll
        for (int ni = 0; ni < 4; ni++) {
            int cw = (wn + ni * 8 + g) * BST;
            bh0[ni] = Bh[cw + t]; bh1[ni] = Bh[cw + 4 + t];
            bl0[ni] = Bl[cw + t]; bl1[ni] = Bl[cw + 4 + t];
        }
#pragma unroll
        for (int mi = 0; mi < 4; mi++) {
            int r0w = (wm + mi * 16 + g) * AST;
            int r1w = r0w + 8 * AST;
            uint32_t ah0 = Ah[r0w + t],     ah1 = Ah[r1w + t];
            uint32_t ah2 = Ah[r0w + 4 + t], ah3 = Ah[r1w + 4 + t];
            if constexpr (F16MODE) {
#pragma unroll
                for (int ni = 0; ni < 4; ni++) {
                    MMA_F16(acc[mi][ni], ah0, ah1, ah2, ah3, bh0[ni], bh1[ni]);
                    MMA_F16(acc[mi][ni], ah0, ah1, ah2, ah3, bl0[ni], bl1[ni]);
                }
            } else {
                uint32_t al0 = Al[r0w + t],     al1 = Al[r1w + t];
                uint32_t al2 = Al[r0w + 4 + t], al3 = Al[r1w + 4 + t];
#pragma unroll
                for (int ni = 0; ni < 4; ni++) {
                    MMA_BF16(acc[mi][ni], ah0, ah1, ah2, ah3, bh0[ni], bh1[ni]);
                    MMA_BF16(acc[mi][ni], ah0, ah1, ah2, ah3, bl0[ni], bl1[ni]);
                    MMA_BF16(acc[mi][ni], al0, al1, al2, al3, bh0[ni], bh1[ni]);
                }
            }
        }
        __syncthreads();
        if (nx) {
            storeTiles();
        }
        __syncthreads();
    }

    // ---- epilogue: fp16 store ----
#pragma unroll
    for (int mi = 0; mi < 4; mi++) {
#pragma unroll
        for (int ni = 0; ni < 4; ni++) {
            int row = bm + wm + mi * 16 + g;
            int col = bn + wn + ni * 8 + 2 * t;
            if (row < M)
                *(__half2*)(Ch + (size_t)row * N + col) =
                    __floats2half2_rn(acc[mi][ni][0], acc[mi][ni][1]);
            if (row + 8 < M)
                *(__half2*)(Ch + (size_t)(row + 8) * N + col) =
                    __floats2half2_rn(acc[mi][ni][2], acc[mi][ni][3]);
        }
    }

    // ---- fused attention-coefficient epilogue ----
    {
        float pas[4][2] = {{0.f,0.f},{0.f,0.f},{0.f,0.f},{0.f,0.f}};
        float pad_[4][2] = {{0.f,0.f},{0.f,0.f},{0.f,0.f},{0.f,0.f}};
#pragma unroll
        for (int ni = 0; ni < 4; ni++) {
#pragma unroll
            for (int j2 = 0; j2 < 2; j2++) {
                int colL = wn + ni * 8 + 2 * t + j2;
                float a = av_src[bn + colL];
                float b = av_dst[bn + colL];
#pragma unroll
                for (int mi = 0; mi < 4; mi++) {
                    pas[mi][0] = fmaf(acc[mi][ni][j2],     a, pas[mi][0]);
                    pas[mi][1] = fmaf(acc[mi][ni][2 + j2], a, pas[mi][1]);
                    pad_[mi][0] = fmaf(acc[mi][ni][j2],     b, pad_[mi][0]);
                    pad_[mi][1] = fmaf(acc[mi][ni][2 + j2], b, pad_[mi][1]);
                }
            }
        }
#pragma unroll
        for (int off = 1; off < 4; off <<= 1) {
#pragma unroll
            for (int mi = 0; mi < 4; mi++) {
#pragma unroll
                for (int h = 0; h < 2; h++) {
                    pas[mi][h] += __shfl_xor_sync(0xffffffffu, pas[mi][h], off);
                    pad_[mi][h] += __shfl_xor_sync(0xffffffffu, pad_[mi][h], off);
                }
            }
        }
        if (t == 0) {
            int q = warp >> 1;   // = wn/32; rows disjoint between warp pairs
#pragma unroll
            for (int mi = 0; mi < 4; mi++) {
#pragma unroll
                for (int h = 0; h < 2; h++) {
                    int row = wm + mi * 16 + h * 8 + g;
                    sAs[q][row] = pas[mi][h];
                    sAd[q][row] = pad_[mi][h];
                }
            }
        }
        __syncthreads();
        if (tid < BM) {
            int row = tid;
            int grow = bm + row;
            if (grow < M) {
                if constexpr (NHEADS == 1) {
                    as_out[grow] = sAs[0][row] + sAs[1][row] + sAs[2][row] + sAs[3][row];
                    ad_out[grow] = sAd[0][row] + sAd[1][row] + sAd[2][row] + sAd[3][row];
                } else {
                    int h0 = blockIdx.x * 2;
                    as_out[(size_t)grow * 4 + h0]     = sAs[0][row] + sAs[1][row];
                    as_out[(size_t)grow * 4 + h0 + 1] = sAs[2][row] + sAs[3][row];
                    ad_out[(size_t)grow * 4 + h0]     = sAd[0][row] + sAd[1][row];
                    ad_out[(size_t)grow * 4 + h0 + 1] = sAd[2][row] + sAd[3][row];
                }
            }
        }
    }
}

// ============================================================================
// layer-1 aggregation: one warp per dst node, single-pass unnormalized
// softmax; fp16 gather in, fp16 out (R14-proven 4-way unroll).
// ============================================================================
__global__ __launch_bounds__(256) void aggregate_l1(
    const int* __restrict__ off, const int* __restrict__ csr,
    const float* __restrict__ as_, const float* __restrict__ ad_,
    const __half* __restrict__ hh, const float* __restrict__ b1,
    __half* __restrict__ out, int n)
{
    int gw = (blockIdx.x * blockDim.x + threadIdx.x) >> 5;
    int lane = threadIdx.x & 31;
    if (gw >= n) return;
    int start = off[gw], end = off[gw + 1];

    float4 adv = *(const float4*)(ad_ + (size_t)gw * 4);
    int hd = lane >> 3;
    float adh = (hd == 0) ? adv.x : (hd == 1) ? adv.y : (hd == 2) ? adv.z : adv.w;

    float acc[8];
#pragma unroll
    for (int j = 0; j < 8; j++) acc[j] = 0.f;
    float dsum = 0.f;

    const uint4* hp = (const uint4*)hh;
    int e = start;
    for (; e + 4 <= end; e += 4) {
        int s0 = csr[e], s1 = csr[e + 1], s2 = csr[e + 2], s3 = csr[e + 3];
        uint4 p0 = hp[(size_t)s0 * 32 + lane];
        uint4 p1 = hp[(size_t)s1 * 32 + lane];
        uint4 p2 = hp[(size_t)s2 * 32 + lane];
        uint4 p3 = hp[(size_t)s3 * 32 + lane];
        float w0 = __expf(lrelu(as_[(size_t)s0 * 4 + hd] + adh));
        float w1 = __expf(lrelu(as_[(size_t)s1 * 4 + hd] + adh));
        float w2 = __expf(lrelu(as_[(size_t)s2 * 4 + hd] + adh));
        float w3 = __expf(lrelu(as_[(size_t)s3 * 4 + hd] + adh));
        dsum += (w0 + w1) + (w2 + w3);
        h2fma(p0.x, w0, acc[0], acc[1]); h2fma(p0.y, w0, acc[2], acc[3]);
        h2fma(p0.z, w0, acc[4], acc[5]); h2fma(p0.w, w0, acc[6], acc[7]);
        h2fma(p1.x, w1, acc[0], acc[1]); h2fma(p1.y, w1, acc[2], acc[3]);
        h2fma(p1.z, w1, acc[4], acc[5]); h2fma(p1.w, w1, acc[6], acc[7]);
        h2fma(p2.x, w2, acc[0], acc[1]); h2fma(p2.y, w2, acc[2], acc[3]);
        h2fma(p2.z, w2, acc[4], acc[5]); h2fma(p2.w, w2, acc[6], acc[7]);
        h2fma(p3.x, w3, acc[0], acc[1]); h2fma(p3.y, w3, acc[2], acc[3]);
        h2fma(p3.z, w3, acc[4], acc[5]); h2fma(p3.w, w3, acc[6], acc[7]);
    }
    for (; e < end; e++) {
        int s0 = csr[e];
        uint4 p0 = hp[(size_t)s0 * 32 + lane];
        float w0 = __expf(lrelu(as_[(size_t)s0 * 4 + hd] + adh));
        dsum += w0;
        h2fma(p0.x, w0, acc[0], acc[1]); h2fma(p0.y, w0, acc[2], acc[3]);
        h2fma(p0.z, w0, acc[4], acc[5]); h2fma(p0.w, w0, acc[6], acc[7]);
    }

    float rh = 1.f / (dsum + 1e-16f);
    float4 bb0 = *(const float4*)(b1 + lane * 8);
    float4 bb1 = *(const float4*)(b1 + lane * 8 + 4);
    float o0 = fmaxf(fmaf(acc[0], rh, bb0.x), 0.f);
    float o1 = fmaxf(fmaf(acc[1], rh, bb0.y), 0.f);
    float o2 = fmaxf(fmaf(acc[2], rh, bb0.z), 0.f);
    float o3 = fmaxf(fmaf(acc[3], rh, bb0.w), 0.f);
    float o4 = fmaxf(fmaf(acc[4], rh, bb1.x), 0.f);
    float o5 = fmaxf(fmaf(acc[5], rh, bb1.y), 0.f);
    float o6 = fmaxf(fmaf(acc[6], rh, bb1.z), 0.f);
    float o7 = fmaxf(fmaf(acc[7], rh, bb1.w), 0.f);
    __half2 q0 = __floats2half2_rn(o0, o1);
    __half2 q1 = __floats2half2_rn(o2, o3);
    __half2 q2 = __floats2half2_rn(o4, o5);
    __half2 q3 = __floats2half2_rn(o6, o7);
    uint4 st;
    st.x = *(uint32_t*)&q0; st.y = *(uint32_t*)&q1;
    st.z = *(uint32_t*)&q2; st.w = *(uint32_t*)&q3;
    *(uint4*)(out + (size_t)gw * 256 + lane * 8) = st;
}

// ============================================================================
// layer-2 aggregation: one warp per dst node, single-pass, fp16 gather
// (R14-proven 4-way unroll).
// ============================================================================
__global__ __launch_bounds__(256) void aggregate_l2(
    const int* __restrict__ off, const int* __restrict__ csr,
    const float* __restrict__ as_, const float* __restrict__ ad_,
    const __half* __restrict__ hh, const float* __restrict__ b2,
    float* __restrict__ out, int n)
{
    int gw = (blockIdx.x * blockDim.x + threadIdx.x) >> 5;
    int lane = threadIdx.x & 31;
    if (gw >= n) return;
    int start = off[gw], end = off[gw + 1];

    float adn = ad_[gw];
    float acc[4] = {0.f, 0.f, 0.f, 0.f};
    float dsum = 0.f;

    const uint2* hp = (const uint2*)hh;
    int e = start;
    for (; e + 4 <= end; e += 4) {
        int s0 = csr[e], s1 = csr[e + 1], s2 = csr[e + 2], s3 = csr[e + 3];
        uint2 p0 = hp[(size_t)s0 * 32 + lane];
        uint2 p1 = hp[(size_t)s1 * 32 + lane];
        uint2 p2 = hp[(size_t)s2 * 32 + lane];
        uint2 p3 = hp[(size_t)s3 * 32 + lane];
        float w0 = __expf(lrelu(as_[s0] + adn));
        float w1 = __expf(lrelu(as_[s1] + adn));
        float w2 = __expf(lrelu(as_[s2] + adn));
        float w3 = __expf(lrelu(as_[s3] + adn));
        dsum += (w0 + w1) + (w2 + w3);
        h2fma(p0.x, w0, acc[0], acc[1]); h2fma(p0.y, w0, acc[2], acc[3]);
        h2fma(p1.x, w1, acc[0], acc[1]); h2fma(p1.y, w1, acc[2], acc[3]);
        h2fma(p2.x, w2, acc[0], acc[1]); h2fma(p2.y, w2, acc[2], acc[3]);
        h2fma(p3.x, w3, acc[0], acc[1]); h2fma(p3.y, w3, acc[2], acc[3]);
    }
    for (; e < end; e++) {
        int s0 = csr[e];
        uint2 p0 = hp[(size_t)s0 * 32 + lane];
        float w0 = __expf(lrelu(as_[s0] + adn));
        dsum += w0;
        h2fma(p0.x, w0, acc[0], acc[1]); h2fma(p0.y, w0, acc[2], acc[3]);
    }

    float r = 1.f / (dsum + 1e-16f);
    float4 bb = *(const float4*)(b2 + lane * 4);
    float4 o = make_float4(fmaf(acc[0], r, bb.x), fmaf(acc[1], r, bb.y),
                           fmaf(acc[2], r, bb.z), fmaf(acc[3], r, bb.w));
    *(float4*)(out + (size_t)gw * OUTC + lane * 4) = o;
}

// ============================================================================
extern "C" void kernel_launch(void* const* d_in, const int* in_sizes, int n_in,
                              void* d_out, int out_size)
{
    const float* x      = (const float*)d_in[0];
    const int*   ei     = (const int*)  d_in[1];
    const float* W1     = (const float*)d_in[2];
    const float* a_src1 = (const float*)d_in[3];
    const float* a_dst1 = (const float*)d_in[4];
    const float* b1     = (const float*)d_in[5];
    const float* W2     = (const float*)d_in[6];
    const float* a_src2 = (const float*)d_in[7];
    const float* a_dst2 = (const float*)d_in[8];
    const float* b2     = (const float*)d_in[9];
    float* out = (float*)d_out;

    int n    = in_sizes[0] / INF_;   // 50000
    int E    = in_sizes[1] / 2;      // 800000
    int Etot = E + n;

    float *as1, *ad1, *as2, *ad2;
    __half *h1h, *out1h, *h2h;
    int *cnt, *off, *part, *csr;
    cudaGetSymbolAddress((void**)&h1h,  g_h1h);
    cudaGetSymbolAddress((void**)&out1h,g_out1h);
    cudaGetSymbolAddress((void**)&as1,  g_as1);
    cudaGetSymbolAddress((void**)&ad1,  g_ad1);
    cudaGetSymbolAddress((void**)&h2h,  g_h2h);
    cudaGetSymbolAddress((void**)&as2,  g_as2);
    cudaGetSymbolAddress((void**)&ad2,  g_ad2);
    cudaGetSymbolAddress((void**)&cnt,  g_cnt);
    cudaGetSymbolAddress((void**)&off,  g_off);
    cudaGetSymbolAddress((void**)&part, g_part);
    cudaGetSymbolAddress((void**)&csr,  g_csr);

    // side stream + fork/join events (created once; host-side handles only)
    static cudaStream_t sB = nullptr;
    static cudaEvent_t  evF = nullptr, evJ = nullptr;
    if (sB == nullptr) {
        cudaStreamCreateWithFlags(&sB, cudaStreamNonBlocking);
        cudaEventCreateWithFlags(&evF, cudaEventDisableTiming);
        cudaEventCreateWithFlags(&evJ, cudaEventDisableTiming);
    }

    const int T = 256;
    auto cdiv = [](int a, int b) { return (a + b - 1) / b; };
    int nchunks = cdiv(n, 1024);

    // ---- fork: CSR build on side stream ----
    cudaEventRecord(evF, 0);
    cudaStreamWaitEvent(sB, evF, 0);

    cudaMemsetAsync(cnt, 0, (size_t)n * sizeof(int), sB);
    count_kernel<<<cdiv(Etot, T * 4), T, 0, sB>>>(ei, E, Etot, cnt);
    scan1_kernel<<<nchunks, 1024, 0, sB>>>(cnt, off, part, n);
    scan_fix_kernel<<<nchunks, 1024, 0, sB>>>(off, cnt, part, n);
    scatter_kernel<<<cdiv(Etot, T * 4), T, 0, sB>>>(ei, E, Etot, cnt, csr);
    cudaEventRecord(evJ, sB);

    // ---- main stream: layer-1 GEMM with fused attn coefficients ----
    {
        dim3 grid(cdiv(HEADS * HID, BN), cdiv(n, BM));
        gemmbf3_kernel<float, 2><<<grid, 256>>>(x, W1, h1h,
                                                a_src1, a_dst1, as1, ad1,
                                                n, HEADS * HID, INF_);
    }

    // ---- join: aggregation needs CSR + alphas + h1h ----
    cudaStreamWaitEvent(0, evJ, 0);
    aggregate_l1<<<cdiv(n * 32, T), T>>>(off, csr, as1, ad1, h1h, b1, out1h, n);

    // ---- layer 2: fp16-A GEMM with fused attn coefficients, then aggregate ----
    {
        dim3 grid(cdiv(OUTC, BN), cdiv(n, BM));
        gemmbf3_kernel<__half, 1><<<grid, 256>>>(out1h, W2, h2h,
                                                 a_src2, a_dst2, as2, ad2,
                                                 n, OUTC, HEADS * HID);
    }
    aggregate_l2<<<cdiv(n * 32, T), T>>>(off, csr, as2, ad2, h2h, b2, out, n);
}